// round 1
// baseline (speedup 1.0000x reference)
#include <cuda_runtime.h>
#include <math.h>

#define NN 10000
#define EE 160000
#define BB 64
#define DD 128
#define MM 32
#define EINN 321
#define H1 642
#define KK 5
#define FH 768
#define F2 256
#define FASTRIDE 644

// ---------------- scratch (zero-initialized device globals) ----------------
__device__ float d_feats[NN*DD];
__device__ float d_ea[EE*65];
__device__ float d_deg[NN];
__device__ float d_FA[NN*FASTRIDE + 256];
__device__ float d_FB[NN*FASTRIDE + 256];
__device__ float d_msum[NN*MM];
__device__ float d_xcat[NN*160];
__device__ float d_fcat[NN*FH];
__device__ float d_f1[NN*F2];
__device__ float d_f2[NN*F2];
__device__ float d_gsum[BB*F2];
__device__ float d_gcnt[BB];

__device__ __forceinline__ float siluf(float x){ return x/(1.f+expf(-x)); }

// ---------------- init / zero kernels ----------------
__global__ void k_zero_init(){
  int i = blockIdx.x*256+threadIdx.x;
  if(i<NN) d_deg[i]=0.f;
  if(i<BB*F2) d_gsum[i]=0.f;
  if(i<BB) d_gcnt[i]=0.f;
}
__global__ void k_zero_msum(){
  int i = blockIdx.x*256+threadIdx.x;
  d_msum[i]=0.f;   // grid sized exactly N*32
}
__global__ void k_feats(const float* __restrict__ emb, const int* __restrict__ atomids){
  int n=blockIdx.x; int c=threadIdx.x;
  float v=emb[atomids[n]*DD+c];
  d_feats[n*DD+c]=v;
  d_fcat[(size_t)n*FH+c]=v;
}
__global__ void k_deg(const int* __restrict__ eidx){
  int e=blockIdx.x*256+threadIdx.x;
  atomicAdd(&d_deg[eidx[EE+e]],1.f);
}
__global__ void k_ea(const float* __restrict__ coords, const int* __restrict__ eidx){
  int e=blockIdx.x*256+threadIdx.x;
  int s=eidx[e], t2=eidx[EE+e];
  float dx=coords[3*s]-coords[3*t2];
  float dy=coords[3*s+1]-coords[3*t2+1];
  float dz=coords[3*s+2]-coords[3*t2+2];
  float d=dx*dx+dy*dy+dz*dz;
  float* o=&d_ea[(size_t)e*65];
  float x=d;
  #pragma unroll
  for(int i=0;i<32;i++){
    o[i]=sinf(x); o[32+i]=cosf(x);
    x*=0.5f;
  }
  o[64]=d;
}

// ---------------- per-layer: FA/FB = feats @ W1[part] ----------------
// grid (11, 157, 2), 256 thr, dynamic smem
__global__ void __launch_bounds__(256) k_fab(const float* __restrict__ keW1,int k){
  extern __shared__ float sm[];
  float* s_f = sm;               // 64*129
  float* s_w = sm + 64*129;      // 128*64
  int zc=blockIdx.z;
  const float* W = keW1 + (size_t)k*EINN*H1 + (size_t)(zc?DD:0)*H1;
  int jc0=blockIdx.x*64, n0=blockIdx.y*64;
  for(int i=threadIdx.x;i<64*DD;i+=256){int r=i>>7,c=i&127;int n=n0+r; s_f[r*129+c]= (n<NN)? d_feats[(size_t)n*DD+c]:0.f;}
  for(int i=threadIdx.x;i<DD*64;i+=256){int p=i>>6,c=i&63;int j=jc0+c; s_w[i]= (j<H1)? W[(size_t)p*H1+j]:0.f;}
  __syncthreads();
  int r0=(threadIdx.x>>4)*4, c0=(threadIdx.x&15)*4;
  float acc[4][4];
  #pragma unroll
  for(int i=0;i<4;i++){acc[i][0]=0;acc[i][1]=0;acc[i][2]=0;acc[i][3]=0;}
  for(int p=0;p<DD;p++){
    float4 w=*(float4*)(s_w+p*64+c0);
    #pragma unroll
    for(int i=0;i<4;i++){ float a=s_f[(r0+i)*129+p];
      acc[i][0]+=a*w.x; acc[i][1]+=a*w.y; acc[i][2]+=a*w.z; acc[i][3]+=a*w.w; }
  }
  float* OUT = zc? d_FB: d_FA;
  #pragma unroll
  for(int i=0;i<4;i++){int n=n0+r0+i; if(n<NN){
    #pragma unroll
    for(int j=0;j<4;j++){int jj=jc0+c0+j; if(jj<FASTRIDE) OUT[(size_t)n*FASTRIDE+jj]=acc[i][j];}
  }}
}

// ---------------- per-layer: fused edge MLP + LN + scatter ----------------
// grid 1250, 256 thr, dynamic smem
__global__ void __launch_bounds__(256) k_edge(const int* __restrict__ eidx,
   const float* __restrict__ keW1,const float* __restrict__ keb1,
   const float* __restrict__ keW2,const float* __restrict__ keb2,
   const float* __restrict__ keng,const float* __restrict__ kenb,int k){
  extern __shared__ float sm[];
  float* s_ea = sm;                    // 128*66 = 8448
  float* s_w1 = s_ea + 8448;           // 65*64  = 4160
  float* s_h  = s_w1 + 4160;           // 128*65 = 8320
  float* s_w2 = s_h + 8320;            // 64*33  = 2112
  float* s_b1 = s_w2 + 2112;           // 64
  float* s_b2 = s_b1 + 64;             // 32
  float* s_g  = s_b2 + 32;             // 32
  float* s_bt = s_g + 32;              // 32
  int* s_dst = (int*)(s_bt+32);        // 128
  int* s_src = s_dst + 128;            // 128
  int tid=threadIdx.x;
  int e0=blockIdx.x*128;
  for(int i=tid;i<128*65;i+=256){ int r=i/65, c=i-r*65; s_ea[r*66+c]=d_ea[(size_t)e0*65 + i]; }
  if(tid<128){ s_dst[tid]=eidx[EE+e0+tid]; s_src[tid]=eidx[e0+tid]; }
  if(tid>=128 && tid<160){ int c=tid-128; s_b2[c]=keb2[k*MM+c]; s_g[c]=keng[k*MM+c]; s_bt[c]=kenb[k*MM+c]; }
  const float* W1c = keW1 + (size_t)k*EINN*H1 + (size_t)256*H1;
  const float* W2  = keW2 + (size_t)k*H1*MM;
  const float* B1  = keb1 + (size_t)k*H1;
  int r0=(tid>>4)*8;
  int c1=(tid&15)*4;
  int c2=(tid&15)*2;
  float acc[8][2];
  #pragma unroll
  for(int i=0;i<8;i++){acc[i][0]=0;acc[i][1]=0;}
  for(int ch=0; ch<11; ch++){
    int jc0=ch*64;
    __syncthreads();
    for(int i=tid;i<65*64;i+=256){int p=i>>6,c=i&63;int j=jc0+c; s_w1[i]=(j<H1)?W1c[(size_t)p*H1+j]:0.f;}
    for(int i=tid;i<64*32;i+=256){int p=i>>5,c=i&31;int j=jc0+p; s_w2[p*33+c]=(j<H1)?W2[(size_t)j*MM+c]:0.f;}
    if(tid<64){int j=jc0+tid; s_b1[tid]=(j<H1)?B1[j]:0.f;}
    __syncthreads();
    float t[8][4];
    #pragma unroll
    for(int i=0;i<8;i++){t[i][0]=0;t[i][1]=0;t[i][2]=0;t[i][3]=0;}
    #pragma unroll 5
    for(int p=0;p<65;p++){
      float4 w=*(float4*)(s_w1+p*64+c1);
      #pragma unroll
      for(int i=0;i<8;i++){ float a=s_ea[(r0+i)*66+p];
        t[i][0]+=a*w.x; t[i][1]+=a*w.y; t[i][2]+=a*w.z; t[i][3]+=a*w.w; }
    }
    float4 bb=*(float4*)(s_b1+c1);
    #pragma unroll
    for(int i=0;i<8;i++){
      int rr=r0+i;
      const float4 fa=*(const float4*)(d_FA+(size_t)s_dst[rr]*FASTRIDE+jc0+c1);
      const float4 fb=*(const float4*)(d_FB+(size_t)s_src[rr]*FASTRIDE+jc0+c1);
      s_h[rr*65+c1+0]=siluf(t[i][0]+bb.x+fa.x+fb.x);
      s_h[rr*65+c1+1]=siluf(t[i][1]+bb.y+fa.y+fb.y);
      s_h[rr*65+c1+2]=siluf(t[i][2]+bb.z+fa.z+fb.z);
      s_h[rr*65+c1+3]=siluf(t[i][3]+bb.w+fa.w+fb.w);
    }
    __syncthreads();
    #pragma unroll 4
    for(int p=0;p<64;p++){
      float w0=s_w2[p*33+c2], w1v=s_w2[p*33+c2+1];
      #pragma unroll
      for(int i=0;i<8;i++){ float a=s_h[(r0+i)*65+p];
        acc[i][0]+=a*w0; acc[i][1]+=a*w1v; }
    }
  }
  float b20=s_b2[c2], b21=s_b2[c2+1];
  float g0=s_g[c2], g1=s_g[c2+1], bt0=s_bt[c2], bt1=s_bt[c2+1];
  #pragma unroll
  for(int i=0;i<8;i++){
    float v0=siluf(acc[i][0]+b20), v1=siluf(acc[i][1]+b21);
    float s=v0+v1, ss=v0*v0+v1*v1;
    #pragma unroll
    for(int o=1;o<16;o<<=1){ s+=__shfl_xor_sync(0xffffffffu,s,o); ss+=__shfl_xor_sync(0xffffffffu,ss,o); }
    float mu=s*(1.f/MM);
    float var=ss*(1.f/MM)-mu*mu;
    float inv=rsqrtf(var+1e-5f);
    float m0=(v0-mu)*inv*g0+bt0;
    float m1=(v1-mu)*inv*g1+bt1;
    float* dsta=&d_msum[(size_t)s_dst[r0+i]*MM];
    atomicAdd(dsta+c2,m0); atomicAdd(dsta+c2+1,m1);
  }
}

// ---------------- per-layer: xcat = [LN(feats) | LN(msum/deg)] ----------------
// grid 1250, 256 thr (warp per node)
__global__ void k_xcat(const float* __restrict__ keng,const float* __restrict__ kenb,
                       const float* __restrict__ kn1g,const float* __restrict__ kn1b,int k){
  int warp=threadIdx.x>>5, lane=threadIdx.x&31;
  int n=blockIdx.x*8+warp;
  const float* g1=kn1g+(size_t)k*128; const float* b1=kn1b+(size_t)k*128;
  float v[4],s=0.f,ss=0.f;
  #pragma unroll
  for(int i=0;i<4;i++){ float x=d_feats[(size_t)n*128+lane+32*i]; v[i]=x; s+=x; ss+=x*x; }
  #pragma unroll
  for(int o=16;o;o>>=1){ s+=__shfl_xor_sync(0xffffffffu,s,o); ss+=__shfl_xor_sync(0xffffffffu,ss,o); }
  float mu=s*(1.f/128), var=ss*(1.f/128)-mu*mu, inv=rsqrtf(var+1e-5f);
  #pragma unroll
  for(int i=0;i<4;i++){ int c=lane+32*i; d_xcat[(size_t)n*160+c]=(v[i]-mu)*inv*g1[c]+b1[c]; }
  float m=d_msum[(size_t)n*MM+lane]/fmaxf(d_deg[n],1.f);
  float s2=m, ss2=m*m;
  #pragma unroll
  for(int o=16;o;o>>=1){ s2+=__shfl_xor_sync(0xffffffffu,s2,o); ss2+=__shfl_xor_sync(0xffffffffu,ss2,o); }
  float mu2=s2*(1.f/MM), var2=ss2*(1.f/MM)-mu2*mu2, inv2=rsqrtf(var2+1e-5f);
  d_xcat[(size_t)n*160+128+lane]=(m-mu2)*inv2*keng[k*MM+lane]+kenb[k*MM+lane];
}

// ---------------- per-layer: fused node MLP + LN + residual ----------------
// grid 157, 256 thr, dynamic smem
__global__ void __launch_bounds__(256) k_node(const float* __restrict__ knW1,const float* __restrict__ knb1,
    const float* __restrict__ knW2,const float* __restrict__ knb2,
    const float* __restrict__ kn2g,const float* __restrict__ kn2b,int k){
  extern __shared__ float sm[];
  float* s_x=sm;            // 64*161=10304
  float* s_h=s_x+10304;     // 64*257=16448
  float* s_w=s_h+16448;     // 256*64=16384
  int tid=threadIdx.x;
  int n0=blockIdx.x*64;
  const float* W1=knW1+(size_t)k*160*256;
  const float* B1=knb1+(size_t)k*256;
  const float* W2=knW2+(size_t)k*256*128;
  const float* B2=knb2+(size_t)k*128;
  const float* G =kn2g+(size_t)k*128;
  const float* BT=kn2b+(size_t)k*128;
  for(int i=tid;i<64*160;i+=256){int r=i/160,c=i-r*160;int n=n0+r; s_x[r*161+c]= (n<NN)? d_xcat[(size_t)n*160+c]:0.f;}
  int r0=(tid>>4)*4, c0=(tid&15)*4;
  for(int oc=0;oc<4;oc++){
    __syncthreads();
    for(int i=tid;i<160*64;i+=256){int p=i>>6,c=i&63; s_w[i]=W1[(size_t)p*256+oc*64+c];}
    __syncthreads();
    float a4[4][4];
    #pragma unroll
    for(int i=0;i<4;i++){a4[i][0]=0;a4[i][1]=0;a4[i][2]=0;a4[i][3]=0;}
    for(int p=0;p<160;p++){
      float4 w=*(float4*)(s_w+p*64+c0);
      #pragma unroll
      for(int i=0;i<4;i++){ float a=s_x[(r0+i)*161+p];
        a4[i][0]+=a*w.x; a4[i][1]+=a*w.y; a4[i][2]+=a*w.z; a4[i][3]+=a*w.w; }
    }
    #pragma unroll
    for(int i=0;i<4;i++){
      #pragma unroll
      for(int j=0;j<4;j++){ int col=oc*64+c0+j;
        s_h[(r0+i)*257+col]=siluf(a4[i][j]+__ldg(&B1[col])); }
    }
  }
  __syncthreads();
  for(int oc=0;oc<2;oc++){
    if(oc) __syncthreads();
    for(int i=tid;i<256*64;i+=256){int p=i>>6,c=i&63; s_w[i]=W2[(size_t)p*128+oc*64+c];}
    __syncthreads();
    float a4[4][4];
    #pragma unroll
    for(int i=0;i<4;i++){a4[i][0]=0;a4[i][1]=0;a4[i][2]=0;a4[i][3]=0;}
    for(int p=0;p<256;p++){
      float4 w=*(float4*)(s_w+p*64+c0);
      #pragma unroll
      for(int i=0;i<4;i++){ float a=s_h[(r0+i)*257+p];
        a4[i][0]+=a*w.x; a4[i][1]+=a*w.y; a4[i][2]+=a*w.z; a4[i][3]+=a*w.w; }
    }
    #pragma unroll
    for(int i=0;i<4;i++){
      #pragma unroll
      for(int j=0;j<4;j++){ int col=oc*64+c0+j;
        s_x[(r0+i)*129+col]=a4[i][j]+__ldg(&B2[col]); }
    }
  }
  __syncthreads();
  int w=tid>>5, lane=tid&31;
  for(int rr=w; rr<64; rr+=8){
    int n=n0+rr;
    float v[4],s=0.f,ss=0.f;
    #pragma unroll
    for(int i=0;i<4;i++){ float x=s_x[rr*129+lane+32*i]; v[i]=x; s+=x; ss+=x*x; }
    #pragma unroll
    for(int o=16;o;o>>=1){ s+=__shfl_xor_sync(0xffffffffu,s,o); ss+=__shfl_xor_sync(0xffffffffu,ss,o); }
    float mu=s*(1.f/128), var=ss*(1.f/128)-mu*mu, inv=rsqrtf(var+1e-5f);
    if(n<NN){
      #pragma unroll
      for(int i=0;i<4;i++){ int c=lane+32*i;
        float nv=(v[i]-mu)*inv*G[c]+BT[c];
        float f=d_feats[(size_t)n*128+c]+nv;
        d_feats[(size_t)n*128+c]=f;
        d_fcat[(size_t)n*FH+(size_t)(k+1)*128+c]=f; }
    }
  }
}

// ---------------- head MLP ----------------
__global__ void __launch_bounds__(256) k_fnn0(const float* __restrict__ W,const float* __restrict__ b){
  __shared__ float s_a[64*65];
  __shared__ float s_w[64*64];
  int tid=threadIdx.x;
  int jc0=blockIdx.x*64, n0=blockIdx.y*64;
  int r0=(tid>>4)*4, c0=(tid&15)*4;
  float acc[4][4];
  #pragma unroll
  for(int i=0;i<4;i++){acc[i][0]=0;acc[i][1]=0;acc[i][2]=0;acc[i][3]=0;}
  for(int ch=0;ch<12;ch++){
    __syncthreads();
    for(int i=tid;i<64*64;i+=256){int r=i>>6,c=i&63;int n=n0+r; s_a[r*65+c]= (n<NN)? siluf(d_fcat[(size_t)n*FH+ch*64+c]) : 0.f;}
    for(int i=tid;i<64*64;i+=256){int p=i>>6,c=i&63; s_w[i]=W[(size_t)(ch*64+p)*F2 + jc0+c];}
    __syncthreads();
    for(int p=0;p<64;p++){
      float4 w=*(float4*)(s_w+p*64+c0);
      #pragma unroll
      for(int i=0;i<4;i++){ float a=s_a[(r0+i)*65+p];
        acc[i][0]+=a*w.x; acc[i][1]+=a*w.y; acc[i][2]+=a*w.z; acc[i][3]+=a*w.w; }
    }
  }
  #pragma unroll
  for(int i=0;i<4;i++){int n=n0+r0+i; if(n<NN){
    #pragma unroll
    for(int j=0;j<4;j++) d_f1[(size_t)n*F2+jc0+c0+j]=siluf(acc[i][j]+__ldg(&b[jc0+c0+j]));
  }}
}

__global__ void __launch_bounds__(256) k_fnn(const float* __restrict__ W,const float* __restrict__ b,int which){
  __shared__ float s_a[64*65];
  __shared__ float s_w[64*64];
  const float* fin = which? d_f2 : d_f1;
  float* fout = which? d_f1 : d_f2;
  int tid=threadIdx.x;
  int jc0=blockIdx.x*64, n0=blockIdx.y*64;
  int r0=(tid>>4)*4, c0=(tid&15)*4;
  float acc[4][4];
  #pragma unroll
  for(int i=0;i<4;i++){acc[i][0]=0;acc[i][1]=0;acc[i][2]=0;acc[i][3]=0;}
  for(int ch=0;ch<4;ch++){
    __syncthreads();
    for(int i=tid;i<64*64;i+=256){int r=i>>6,c=i&63;int n=n0+r; s_a[r*65+c]= (n<NN)? fin[(size_t)n*F2+ch*64+c] : 0.f;}
    for(int i=tid;i<64*64;i+=256){int p=i>>6,c=i&63; s_w[i]=W[(size_t)(ch*64+p)*F2 + jc0+c];}
    __syncthreads();
    for(int p=0;p<64;p++){
      float4 w=*(float4*)(s_w+p*64+c0);
      #pragma unroll
      for(int i=0;i<4;i++){ float a=s_a[(r0+i)*65+p];
        acc[i][0]+=a*w.x; acc[i][1]+=a*w.y; acc[i][2]+=a*w.z; acc[i][3]+=a*w.w; }
    }
  }
  #pragma unroll
  for(int i=0;i<4;i++){int n=n0+r0+i; if(n<NN){
    #pragma unroll
    for(int j=0;j<4;j++) fout[(size_t)n*F2+jc0+c0+j]=siluf(acc[i][j]+__ldg(&b[jc0+c0+j]));
  }}
}

__global__ void k_pool(const int* __restrict__ batch){
  int n=blockIdx.x; int c=threadIdx.x;
  int b=batch[n];
  atomicAdd(&d_gsum[b*F2+c], d_f1[(size_t)n*F2+c]);
  if(c==0) atomicAdd(&d_gcnt[b],1.f);
}

__global__ void k_final(const float* __restrict__ gW0,const float* __restrict__ gb0,
                        const float* __restrict__ gW1,const float* __restrict__ gb1,
                        const float* __restrict__ gW2,const float* __restrict__ gb2,
                        float* __restrict__ out){
  __shared__ float s_g[256], s_h[256], s_red[8];
  int b=blockIdx.x, t=threadIdx.x;
  float cnt=fmaxf(d_gcnt[b],1.f);
  s_g[t]=d_gsum[b*F2+t]/cnt;
  __syncthreads();
  float a=gb0[t];
  #pragma unroll 8
  for(int p=0;p<256;p++) a+=s_g[p]*gW0[p*256+t];
  s_h[t]=siluf(a);
  __syncthreads();
  a=gb1[t];
  #pragma unroll 8
  for(int p=0;p<256;p++) a+=s_h[p]*gW1[p*256+t];
  float h=siluf(a);
  float v=h*gW2[t];
  #pragma unroll
  for(int o=16;o;o>>=1) v+=__shfl_xor_sync(0xffffffffu,v,o);
  if((t&31)==0) s_red[t>>5]=v;
  __syncthreads();
  if(t==0){ float tot=0.f;
    #pragma unroll
    for(int i=0;i<8;i++) tot+=s_red[i];
    out[b]=tot+gb2[0]; }
}

// ---------------- host ----------------
extern "C" void kernel_launch(void* const* d_in, const int* in_sizes, int n_in,
                              void* d_out, int out_size){
  const float* coords =(const float*)d_in[0];
  const int*   atomids=(const int*)d_in[1];
  const int*   eidx   =(const int*)d_in[2];
  const int*   batch  =(const int*)d_in[3];
  int s = (in_sizes[4]==11*DD) ? 4 : 5;   // skip num_graphs scalar if present
  const float* emb =(const float*)d_in[s+0];
  const float* keW1=(const float*)d_in[s+1];
  const float* keb1=(const float*)d_in[s+2];
  const float* keW2=(const float*)d_in[s+3];
  const float* keb2=(const float*)d_in[s+4];
  const float* keng=(const float*)d_in[s+5];
  const float* kenb=(const float*)d_in[s+6];
  const float* kn1g=(const float*)d_in[s+7];
  const float* kn1b=(const float*)d_in[s+8];
  const float* knW1=(const float*)d_in[s+9];
  const float* knb1=(const float*)d_in[s+10];
  const float* knW2=(const float*)d_in[s+11];
  const float* knb2=(const float*)d_in[s+12];
  const float* kn2g=(const float*)d_in[s+13];
  const float* kn2b=(const float*)d_in[s+14];
  const float* fW0 =(const float*)d_in[s+15];
  const float* fb0 =(const float*)d_in[s+16];
  const float* fW1 =(const float*)d_in[s+17];
  const float* fb1 =(const float*)d_in[s+18];
  const float* fW2 =(const float*)d_in[s+19];
  const float* fb2 =(const float*)d_in[s+20];
  const float* gW0 =(const float*)d_in[s+21];
  const float* gb0 =(const float*)d_in[s+22];
  const float* gW1 =(const float*)d_in[s+23];
  const float* gb1 =(const float*)d_in[s+24];
  const float* gW2 =(const float*)d_in[s+25];
  const float* gb2 =(const float*)d_in[s+26];
  float* out=(float*)d_out;

  const int FAB_SM  = (64*129 + 128*64)*4;                 // 65792
  const int EDGE_SM = (8448+4160+8320+2112+64+32+32+32)*4 + 256*4; // 93824
  const int NODE_SM = (10304+16448+16384)*4;               // 172544
  cudaFuncSetAttribute(k_fab,  cudaFuncAttributeMaxDynamicSharedMemorySize, FAB_SM);
  cudaFuncSetAttribute(k_edge, cudaFuncAttributeMaxDynamicSharedMemorySize, EDGE_SM);
  cudaFuncSetAttribute(k_node, cudaFuncAttributeMaxDynamicSharedMemorySize, NODE_SM);

  k_zero_init<<<65,256>>>();
  k_feats<<<NN,128>>>(emb,atomids);
  k_deg<<<EE/256,256>>>(eidx);
  k_ea<<<EE/256,256>>>(coords,eidx);
  for(int k=0;k<KK;k++){
    k_zero_msum<<<(NN*MM)/256,256>>>();
    k_fab<<<dim3(11,157,2),256,FAB_SM>>>(keW1,k);
    k_edge<<<EE/128,256,EDGE_SM>>>(eidx,keW1,keb1,keW2,keb2,keng,kenb,k);
    k_xcat<<<NN/8,256>>>(keng,kenb,kn1g,kn1b,k);
    k_node<<<157,256,NODE_SM>>>(knW1,knb1,knW2,knb2,kn2g,kn2b,k);
  }
  k_fnn0<<<dim3(4,157),256>>>(fW0,fb0);
  k_fnn<<<dim3(4,157),256>>>(fW1,fb1,0);
  k_fnn<<<dim3(4,157),256>>>(fW2,fb2,1);
  k_pool<<<NN,256>>>(batch);
  k_final<<<BB,256>>>(gW0,gb0,gW1,gb1,gW2,gb2,out);
}